// round 4
// baseline (speedup 1.0000x reference)
#include <cuda_runtime.h>

#define BB   4
#define SS   1568
#define DD   1024
#define HH   16
#define HDIM 64
#define MTOT (BB*SS)          // 6272

#define QT 64                 // query tile
#define KT 32                 // key/value tile
#define QPITCH (HDIM+4)       // 68 floats, float4-aligned rows
#define PPITCH (KT+4)         // 36 floats

// -------- scratch (no allocation allowed; __device__ globals) --------
__device__ float g_q[BB*HH*SS*HDIM];
__device__ float g_k[BB*HH*SS*HDIM];
__device__ float g_v[BB*HH*SS*HDIM];
__device__ float g_ctx[MTOT*DD];

// ============================================================================
// SGEMM: C[m,n] = sum_k A[m,k] * W[n,k] + bias[n]
//   mode 0/1/2: A = Ain (hidden_states), write g_q/g_k/g_v in [B,H,S,HD]
//   mode 3:     A = g_ctx,               write outp as plain [M,D]
// Tile 64x64, BK=16, 256 threads, 4x4 per thread.
// ============================================================================
__global__ void __launch_bounds__(256) sgemm_kernel(
    const float* __restrict__ Ain, const float* __restrict__ W,
    const float* __restrict__ bias, float* __restrict__ outp, int mode)
{
    __shared__ float As[16][68];   // As[k][m], padded
    __shared__ float Bs[16][68];   // Bs[k][n], padded

    const float* A = (mode == 3) ? g_ctx : Ain;

    const int tid = threadIdx.x;
    const int m0 = blockIdx.y * 64;
    const int n0 = blockIdx.x * 64;
    const int lr = tid >> 2;          // 0..63 row within tile
    const int lc = (tid & 3) << 2;    // k offset 0,4,8,12
    const int ty = tid >> 4;          // 0..15
    const int tx = tid & 15;          // 0..15

    float acc[4][4];
#pragma unroll
    for (int i = 0; i < 4; i++)
#pragma unroll
        for (int j = 0; j < 4; j++) acc[i][j] = 0.f;

    const float* Aptr = A + (size_t)(m0 + lr) * DD + lc;
    const float* Wptr = W + (size_t)(n0 + lr) * DD + lc;

    for (int k0 = 0; k0 < DD; k0 += 16) {
        float4 av = *(const float4*)(Aptr + k0);
        float4 wv = *(const float4*)(Wptr + k0);
        As[lc + 0][lr] = av.x; As[lc + 1][lr] = av.y;
        As[lc + 2][lr] = av.z; As[lc + 3][lr] = av.w;
        Bs[lc + 0][lr] = wv.x; Bs[lc + 1][lr] = wv.y;
        Bs[lc + 2][lr] = wv.z; Bs[lc + 3][lr] = wv.w;
        __syncthreads();

#pragma unroll
        for (int kk = 0; kk < 16; kk++) {
            float4 a4 = *(const float4*)&As[kk][ty << 2];
            float4 b4 = *(const float4*)&Bs[kk][tx << 2];
            float ar[4] = {a4.x, a4.y, a4.z, a4.w};
            float br[4] = {b4.x, b4.y, b4.z, b4.w};
#pragma unroll
            for (int i = 0; i < 4; i++)
#pragma unroll
                for (int j = 0; j < 4; j++)
                    acc[i][j] = fmaf(ar[i], br[j], acc[i][j]);
        }
        __syncthreads();
    }

    // epilogue
    float4 bv = *(const float4*)&bias[n0 + (tx << 2)];
#pragma unroll
    for (int i = 0; i < 4; i++) {
        int m = m0 + (ty << 2) + i;
        float4 r;
        r.x = acc[i][0] + bv.x; r.y = acc[i][1] + bv.y;
        r.z = acc[i][2] + bv.z; r.w = acc[i][3] + bv.w;
        if (mode == 3) {
            *(float4*)&outp[(size_t)m * DD + n0 + (tx << 2)] = r;
        } else {
            int b = m / SS, s = m % SS;
            int h = n0 >> 6;                       // BN == HD == 64
            float* dst = (mode == 0) ? g_q : (mode == 1) ? g_k : g_v;
            *(float4*)&dst[(size_t)(((b * HH + h) * SS + s)) * HDIM + (tx << 2)] = r;
        }
    }
}

// ============================================================================
// Flash attention: per (b,h), 64-query tiles, loop over 32-key tiles.
// Online softmax. ctx written to g_ctx in [B,S,D] layout.
// 256 threads: ty=tid/16 owns q rows ty*4+{0..3}; tx=tid%16.
// Score cols per thread: {tx, tx+16}. Output hd cols per thread: tx*4+{0..3}.
// ============================================================================
__global__ void __launch_bounds__(256) attn_kernel()
{
    __shared__ float Qs[QT][QPITCH];     // 64x68
    __shared__ float Ks[KT][QPITCH];     // 32x68
    __shared__ float Vs[KT][QPITCH];     // 32x68
    __shared__ float Ps[QT][PPITCH];     // 64x36

    const int b  = blockIdx.z;
    const int h  = blockIdx.y;
    const int q0 = blockIdx.x * QT;
    const int tid = threadIdx.x;
    const int ty = tid >> 4;
    const int tx = tid & 15;

    const float* qb = g_q + (size_t)((b * HH + h) * SS) * HDIM;
    const float* kb = g_k + (size_t)((b * HH + h) * SS) * HDIM;
    const float* vb = g_v + (size_t)((b * HH + h) * SS) * HDIM;

    // load Q tile (zeros for rows beyond S)
#pragma unroll
    for (int i = 0; i < 4; i++) {
        int idx = tid + i * 256;           // float4 index 0..1023
        int r = idx >> 4, c = (idx & 15) << 2;
        int qr = q0 + r;
        float4 v4 = make_float4(0.f, 0.f, 0.f, 0.f);
        if (qr < SS) v4 = *(const float4*)&qb[(size_t)qr * HDIM + c];
        *(float4*)&Qs[r][c] = v4;
    }

    float m_i[4], l_i[4], acc[4][4];
#pragma unroll
    for (int i = 0; i < 4; i++) {
        m_i[i] = -1e30f; l_i[i] = 0.f;
#pragma unroll
        for (int j = 0; j < 4; j++) acc[i][j] = 0.f;
    }
    const float scale = 0.125f;  // 1/sqrt(64)
    const int nkt = (SS + KT - 1) / KT;  // 49

    for (int kt = 0; kt < nkt; kt++) {
        int k0 = kt * KT;
        // load K/V tiles (32x64 each)
#pragma unroll
        for (int i = 0; i < 2; i++) {
            int idx = tid + i * 256;       // float4 index 0..511
            int r = idx >> 4, c = (idx & 15) << 2;
            int kr = k0 + r;
            float4 kv4 = make_float4(0.f, 0.f, 0.f, 0.f);
            float4 vv4 = kv4;
            if (kr < SS) {
                kv4 = *(const float4*)&kb[(size_t)kr * HDIM + c];
                vv4 = *(const float4*)&vb[(size_t)kr * HDIM + c];
            }
            *(float4*)&Ks[r][c] = kv4;
            *(float4*)&Vs[r][c] = vv4;
        }
        __syncthreads();

        // scores: s[i][j] for q row (ty*4+i), key col (tx + 16*j)
        float s[4][2];
#pragma unroll
        for (int i = 0; i < 4; i++) { s[i][0] = 0.f; s[i][1] = 0.f; }
#pragma unroll
        for (int d4 = 0; d4 < 16; d4++) {
            float4 qv[4], kv[2];
#pragma unroll
            for (int i = 0; i < 4; i++) qv[i] = *(const float4*)&Qs[ty * 4 + i][d4 << 2];
            kv[0] = *(const float4*)&Ks[tx][d4 << 2];
            kv[1] = *(const float4*)&Ks[tx + 16][d4 << 2];
#pragma unroll
            for (int i = 0; i < 4; i++) {
#pragma unroll
                for (int j = 0; j < 2; j++) {
                    s[i][j] = fmaf(qv[i].x, kv[j].x, s[i][j]);
                    s[i][j] = fmaf(qv[i].y, kv[j].y, s[i][j]);
                    s[i][j] = fmaf(qv[i].z, kv[j].z, s[i][j]);
                    s[i][j] = fmaf(qv[i].w, kv[j].w, s[i][j]);
                }
            }
        }
        // scale + mask
#pragma unroll
        for (int i = 0; i < 4; i++) {
#pragma unroll
            for (int j = 0; j < 2; j++) {
                s[i][j] *= scale;
                if (k0 + tx + 16 * j >= SS) s[i][j] = -1e30f;
            }
        }

        // online softmax per q row (reduce across the 16 tx threads)
#pragma unroll
        for (int i = 0; i < 4; i++) {
            float mx = fmaxf(s[i][0], s[i][1]);
#pragma unroll
            for (int off = 8; off > 0; off >>= 1)
                mx = fmaxf(mx, __shfl_xor_sync(0xffffffffu, mx, off, 16));
            float mnew = fmaxf(m_i[i], mx);
            float alpha = __expf(m_i[i] - mnew);
            float p0 = __expf(s[i][0] - mnew);
            float p1 = __expf(s[i][1] - mnew);
            float ls = p0 + p1;
#pragma unroll
            for (int off = 8; off > 0; off >>= 1)
                ls += __shfl_xor_sync(0xffffffffu, ls, off, 16);
            l_i[i] = l_i[i] * alpha + ls;
            m_i[i] = mnew;
#pragma unroll
            for (int c = 0; c < 4; c++) acc[i][c] *= alpha;
            Ps[ty * 4 + i][tx]      = p0;
            Ps[ty * 4 + i][tx + 16] = p1;
        }
        __syncthreads();

        // acc[i][c] += sum_k Ps[r][k] * Vs[k][tx*4+c]
#pragma unroll
        for (int k4 = 0; k4 < KT / 4; k4++) {
            float4 pv[4];
#pragma unroll
            for (int i = 0; i < 4; i++)
                pv[i] = *(const float4*)&Ps[ty * 4 + i][k4 << 2];
#pragma unroll
            for (int kk = 0; kk < 4; kk++) {
                float4 vv = *(const float4*)&Vs[(k4 << 2) + kk][tx << 2];
#pragma unroll
                for (int i = 0; i < 4; i++) {
                    float p = (kk == 0) ? pv[i].x : (kk == 1) ? pv[i].y
                            : (kk == 2) ? pv[i].z : pv[i].w;
                    acc[i][0] = fmaf(p, vv.x, acc[i][0]);
                    acc[i][1] = fmaf(p, vv.y, acc[i][1]);
                    acc[i][2] = fmaf(p, vv.z, acc[i][2]);
                    acc[i][3] = fmaf(p, vv.w, acc[i][3]);
                }
            }
        }
        __syncthreads();
    }

    // epilogue: normalize and write ctx in [B,S,D] layout
#pragma unroll
    for (int i = 0; i < 4; i++) {
        int qr = q0 + ty * 4 + i;
        if (qr < SS) {
            float inv = 1.0f / l_i[i];
            float4 r;
            r.x = acc[i][0] * inv; r.y = acc[i][1] * inv;
            r.z = acc[i][2] * inv; r.w = acc[i][3] * inv;
            *(float4*)&g_ctx[(size_t)(b * SS + qr) * DD + h * HDIM + (tx << 2)] = r;
        }
    }
}

// ============================================================================
extern "C" void kernel_launch(void* const* d_in, const int* in_sizes, int n_in,
                              void* d_out, int out_size)
{
    const float* x  = (const float*)d_in[0];
    const float* Wq = (const float*)d_in[1];
    const float* bq = (const float*)d_in[2];
    const float* Wk = (const float*)d_in[3];
    const float* bk = (const float*)d_in[4];
    const float* Wv = (const float*)d_in[5];
    const float* bv = (const float*)d_in[6];
    const float* Wp = (const float*)d_in[7];
    const float* bp = (const float*)d_in[8];
    float* out = (float*)d_out;

    dim3 gg(DD / 64, MTOT / 64);   // 16 x 98
    sgemm_kernel<<<gg, 256>>>(x, Wq, bq, nullptr, 0);
    sgemm_kernel<<<gg, 256>>>(x, Wk, bk, nullptr, 1);
    sgemm_kernel<<<gg, 256>>>(x, Wv, bv, nullptr, 2);

    dim3 ga((SS + QT - 1) / QT, HH, BB);  // 25 x 16 x 4
    attn_kernel<<<ga, 256>>>();

    sgemm_kernel<<<gg, 256>>>(nullptr, Wp, bp, out, 3);
}

// round 5
// speedup vs baseline: 1.0010x; 1.0010x over previous
#include <cuda_runtime.h>

#define BB   4
#define SS   1568
#define DD   1024
#define HH   16
#define HDIM 64
#define MTOT (BB*SS)          // 6272

#define QT 64                 // query tile
#define KT 32                 // key/value tile
#define QPITCH (HDIM+4)       // 68 floats, float4-aligned rows
#define PPITCH (KT+4)         // 36 floats

// -------- scratch (no allocation allowed; __device__ globals) --------
__device__ float g_q[BB*HH*SS*HDIM];
__device__ float g_k[BB*HH*SS*HDIM];
__device__ float g_v[BB*HH*SS*HDIM];
__device__ float g_ctx[MTOT*DD];

// ============================================================================
// SGEMM: C[m,n] = sum_k A[m,k] * W[n,k] + bias[n]
//   mode 0/1/2: A = Ain (hidden_states), write g_q/g_k/g_v in [B,H,S,HD]
//   mode 3:     A = g_ctx,               write outp as plain [M,D]
// Tile 64x64, BK=16, 256 threads, 4x4 per thread.
// ============================================================================
__global__ void __launch_bounds__(256) sgemm_kernel(
    const float* __restrict__ Ain, const float* __restrict__ W,
    const float* __restrict__ bias, float* __restrict__ outp, int mode)
{
    __shared__ float As[16][68];   // As[k][m], padded
    __shared__ float Bs[16][68];   // Bs[k][n], padded

    const float* A = (mode == 3) ? g_ctx : Ain;

    const int tid = threadIdx.x;
    const int m0 = blockIdx.y * 64;
    const int n0 = blockIdx.x * 64;
    const int lr = tid >> 2;          // 0..63 row within tile
    const int lc = (tid & 3) << 2;    // k offset 0,4,8,12
    const int ty = tid >> 4;          // 0..15
    const int tx = tid & 15;          // 0..15

    float acc[4][4];
#pragma unroll
    for (int i = 0; i < 4; i++)
#pragma unroll
        for (int j = 0; j < 4; j++) acc[i][j] = 0.f;

    const float* Aptr = A + (size_t)(m0 + lr) * DD + lc;
    const float* Wptr = W + (size_t)(n0 + lr) * DD + lc;

    for (int k0 = 0; k0 < DD; k0 += 16) {
        float4 av = *(const float4*)(Aptr + k0);
        float4 wv = *(const float4*)(Wptr + k0);
        As[lc + 0][lr] = av.x; As[lc + 1][lr] = av.y;
        As[lc + 2][lr] = av.z; As[lc + 3][lr] = av.w;
        Bs[lc + 0][lr] = wv.x; Bs[lc + 1][lr] = wv.y;
        Bs[lc + 2][lr] = wv.z; Bs[lc + 3][lr] = wv.w;
        __syncthreads();

#pragma unroll
        for (int kk = 0; kk < 16; kk++) {
            float4 a4 = *(const float4*)&As[kk][ty << 2];
            float4 b4 = *(const float4*)&Bs[kk][tx << 2];
            float ar[4] = {a4.x, a4.y, a4.z, a4.w};
            float br[4] = {b4.x, b4.y, b4.z, b4.w};
#pragma unroll
            for (int i = 0; i < 4; i++)
#pragma unroll
                for (int j = 0; j < 4; j++)
                    acc[i][j] = fmaf(ar[i], br[j], acc[i][j]);
        }
        __syncthreads();
    }

    // epilogue
    float4 bv = *(const float4*)&bias[n0 + (tx << 2)];
#pragma unroll
    for (int i = 0; i < 4; i++) {
        int m = m0 + (ty << 2) + i;
        float4 r;
        r.x = acc[i][0] + bv.x; r.y = acc[i][1] + bv.y;
        r.z = acc[i][2] + bv.z; r.w = acc[i][3] + bv.w;
        if (mode == 3) {
            *(float4*)&outp[(size_t)m * DD + n0 + (tx << 2)] = r;
        } else {
            int b = m / SS, s = m % SS;
            int h = n0 >> 6;                       // BN == HD == 64
            float* dst = (mode == 0) ? g_q : (mode == 1) ? g_k : g_v;
            *(float4*)&dst[(size_t)(((b * HH + h) * SS + s)) * HDIM + (tx << 2)] = r;
        }
    }
}

// ============================================================================
// Flash attention: per (b,h), 64-query tiles, loop over 32-key tiles.
// Online softmax. ctx written to g_ctx in [B,S,D] layout.
// 256 threads: ty=tid/16 owns q rows ty*4+{0..3}; tx=tid%16.
// Score cols per thread: {tx, tx+16}. Output hd cols per thread: tx*4+{0..3}.
// ============================================================================
__global__ void __launch_bounds__(256) attn_kernel()
{
    __shared__ float Qs[QT][QPITCH];     // 64x68
    __shared__ float Ks[KT][QPITCH];     // 32x68
    __shared__ float Vs[KT][QPITCH];     // 32x68
    __shared__ float Ps[QT][PPITCH];     // 64x36

    const int b  = blockIdx.z;
    const int h  = blockIdx.y;
    const int q0 = blockIdx.x * QT;
    const int tid = threadIdx.x;
    const int ty = tid >> 4;
    const int tx = tid & 15;

    const float* qb = g_q + (size_t)((b * HH + h) * SS) * HDIM;
    const float* kb = g_k + (size_t)((b * HH + h) * SS) * HDIM;
    const float* vb = g_v + (size_t)((b * HH + h) * SS) * HDIM;

    // load Q tile (zeros for rows beyond S)
#pragma unroll
    for (int i = 0; i < 4; i++) {
        int idx = tid + i * 256;           // float4 index 0..1023
        int r = idx >> 4, c = (idx & 15) << 2;
        int qr = q0 + r;
        float4 v4 = make_float4(0.f, 0.f, 0.f, 0.f);
        if (qr < SS) v4 = *(const float4*)&qb[(size_t)qr * HDIM + c];
        *(float4*)&Qs[r][c] = v4;
    }

    float m_i[4], l_i[4], acc[4][4];
#pragma unroll
    for (int i = 0; i < 4; i++) {
        m_i[i] = -1e30f; l_i[i] = 0.f;
#pragma unroll
        for (int j = 0; j < 4; j++) acc[i][j] = 0.f;
    }
    const float scale = 0.125f;  // 1/sqrt(64)
    const int nkt = (SS + KT - 1) / KT;  // 49

    for (int kt = 0; kt < nkt; kt++) {
        int k0 = kt * KT;
        // load K/V tiles (32x64 each)
#pragma unroll
        for (int i = 0; i < 2; i++) {
            int idx = tid + i * 256;       // float4 index 0..511
            int r = idx >> 4, c = (idx & 15) << 2;
            int kr = k0 + r;
            float4 kv4 = make_float4(0.f, 0.f, 0.f, 0.f);
            float4 vv4 = kv4;
            if (kr < SS) {
                kv4 = *(const float4*)&kb[(size_t)kr * HDIM + c];
                vv4 = *(const float4*)&vb[(size_t)kr * HDIM + c];
            }
            *(float4*)&Ks[r][c] = kv4;
            *(float4*)&Vs[r][c] = vv4;
        }
        __syncthreads();

        // scores: s[i][j] for q row (ty*4+i), key col (tx + 16*j)
        float s[4][2];
#pragma unroll
        for (int i = 0; i < 4; i++) { s[i][0] = 0.f; s[i][1] = 0.f; }
#pragma unroll
        for (int d4 = 0; d4 < 16; d4++) {
            float4 qv[4], kv[2];
#pragma unroll
            for (int i = 0; i < 4; i++) qv[i] = *(const float4*)&Qs[ty * 4 + i][d4 << 2];
            kv[0] = *(const float4*)&Ks[tx][d4 << 2];
            kv[1] = *(const float4*)&Ks[tx + 16][d4 << 2];
#pragma unroll
            for (int i = 0; i < 4; i++) {
#pragma unroll
                for (int j = 0; j < 2; j++) {
                    s[i][j] = fmaf(qv[i].x, kv[j].x, s[i][j]);
                    s[i][j] = fmaf(qv[i].y, kv[j].y, s[i][j]);
                    s[i][j] = fmaf(qv[i].z, kv[j].z, s[i][j]);
                    s[i][j] = fmaf(qv[i].w, kv[j].w, s[i][j]);
                }
            }
        }
        // scale + mask
#pragma unroll
        for (int i = 0; i < 4; i++) {
#pragma unroll
            for (int j = 0; j < 2; j++) {
                s[i][j] *= scale;
                if (k0 + tx + 16 * j >= SS) s[i][j] = -1e30f;
            }
        }

        // online softmax per q row (reduce across the 16 tx threads)
#pragma unroll
        for (int i = 0; i < 4; i++) {
            float mx = fmaxf(s[i][0], s[i][1]);
#pragma unroll
            for (int off = 8; off > 0; off >>= 1)
                mx = fmaxf(mx, __shfl_xor_sync(0xffffffffu, mx, off, 16));
            float mnew = fmaxf(m_i[i], mx);
            float alpha = __expf(m_i[i] - mnew);
            float p0 = __expf(s[i][0] - mnew);
            float p1 = __expf(s[i][1] - mnew);
            float ls = p0 + p1;
#pragma unroll
            for (int off = 8; off > 0; off >>= 1)
                ls += __shfl_xor_sync(0xffffffffu, ls, off, 16);
            l_i[i] = l_i[i] * alpha + ls;
            m_i[i] = mnew;
#pragma unroll
            for (int c = 0; c < 4; c++) acc[i][c] *= alpha;
            Ps[ty * 4 + i][tx]      = p0;
            Ps[ty * 4 + i][tx + 16] = p1;
        }
        __syncthreads();

        // acc[i][c] += sum_k Ps[r][k] * Vs[k][tx*4+c]
#pragma unroll
        for (int k4 = 0; k4 < KT / 4; k4++) {
            float4 pv[4];
#pragma unroll
            for (int i = 0; i < 4; i++)
                pv[i] = *(const float4*)&Ps[ty * 4 + i][k4 << 2];
#pragma unroll
            for (int kk = 0; kk < 4; kk++) {
                float4 vv = *(const float4*)&Vs[(k4 << 2) + kk][tx << 2];
#pragma unroll
                for (int i = 0; i < 4; i++) {
                    float p = (kk == 0) ? pv[i].x : (kk == 1) ? pv[i].y
                            : (kk == 2) ? pv[i].z : pv[i].w;
                    acc[i][0] = fmaf(p, vv.x, acc[i][0]);
                    acc[i][1] = fmaf(p, vv.y, acc[i][1]);
                    acc[i][2] = fmaf(p, vv.z, acc[i][2]);
                    acc[i][3] = fmaf(p, vv.w, acc[i][3]);
                }
            }
        }
        __syncthreads();
    }

    // epilogue: normalize and write ctx in [B,S,D] layout
#pragma unroll
    for (int i = 0; i < 4; i++) {
        int qr = q0 + ty * 4 + i;
        if (qr < SS) {
            float inv = 1.0f / l_i[i];
            float4 r;
            r.x = acc[i][0] * inv; r.y = acc[i][1] * inv;
            r.z = acc[i][2] * inv; r.w = acc[i][3] * inv;
            *(float4*)&g_ctx[(size_t)(b * SS + qr) * DD + h * HDIM + (tx << 2)] = r;
        }
    }
}

// ============================================================================
extern "C" void kernel_launch(void* const* d_in, const int* in_sizes, int n_in,
                              void* d_out, int out_size)
{
    const float* x  = (const float*)d_in[0];
    const float* Wq = (const float*)d_in[1];
    const float* bq = (const float*)d_in[2];
    const float* Wk = (const float*)d_in[3];
    const float* bk = (const float*)d_in[4];
    const float* Wv = (const float*)d_in[5];
    const float* bv = (const float*)d_in[6];
    const float* Wp = (const float*)d_in[7];
    const float* bp = (const float*)d_in[8];
    float* out = (float*)d_out;

    dim3 gg(DD / 64, MTOT / 64);   // 16 x 98
    sgemm_kernel<<<gg, 256>>>(x, Wq, bq, nullptr, 0);
    sgemm_kernel<<<gg, 256>>>(x, Wk, bk, nullptr, 1);
    sgemm_kernel<<<gg, 256>>>(x, Wv, bv, nullptr, 2);

    dim3 ga((SS + QT - 1) / QT, HH, BB);  // 25 x 16 x 4
    attn_kernel<<<ga, 256>>>();

    sgemm_kernel<<<gg, 256>>>(nullptr, Wp, bp, out, 3);
}

// round 9
// speedup vs baseline: 1.6077x; 1.6061x over previous
#include <cuda_runtime.h>
#include <cstdint>

#define BB   4
#define SS   1568
#define DD   1024
#define HH   16
#define HDIM 64
#define MTOT (BB*SS)          // 6272

#define QT 64                 // query tile (attention)
#define KT 32                 // key/value tile
#define QPITCH (HDIM+4)
#define PPITCH (KT+4)

// -------- scratch (no allocation allowed; __device__ globals) --------
__device__ float g_q[BB*HH*SS*HDIM];
__device__ float g_k[BB*HH*SS*HDIM];
__device__ float g_v[BB*HH*SS*HDIM];
__device__ float g_ctx[MTOT*DD];

// ============================================================================
// tf32 helpers (sm_80-class PTX — compiles under compute_103)
// ============================================================================
__device__ __forceinline__ uint32_t f2tf(float f) {
    uint32_t u;
    asm("cvt.rna.tf32.f32 %0, %1;" : "=r"(u) : "f"(f));
    return u;
}

#define MMA_TF32(c, a, b) \
    asm volatile("mma.sync.aligned.m16n8k8.row.col.f32.tf32.tf32.f32 " \
        "{%0,%1,%2,%3}, {%4,%5,%6,%7}, {%8,%9}, {%0,%1,%2,%3};" \
        : "+f"((c)[0]), "+f"((c)[1]), "+f"((c)[2]), "+f"((c)[3]) \
        : "r"((a)[0]), "r"((a)[1]), "r"((a)[2]), "r"((a)[3]), \
          "r"((b)[0]), "r"((b)[1]))

// ============================================================================
// tf32 tensor-core GEMM: C[m,n] = sum_k A[m,k]*W[n,k] + bias[n]
// BM=128, BN=64, BK=32. 256 threads = 8 warps (4M x 2N), warp tile 32x64? no:
// warp tile 32(M) x 32(N): 2 m16-tiles x 4 n8-tiles per k8-step.
// Smem: XOR-swizzled (pk = k ^ ((row&7)<<2)), stride 32, conflict-free.
//   mode 0/1/2: A = Ain, write g_q/g_k/g_v in [B,H,S,HD]
//   mode 3:     A = g_ctx, write outp [M,D]
// ============================================================================
#define NCHUNK 32   // 1024 / 32

__global__ void __launch_bounds__(256, 2) gemm_tf32(
    const float* __restrict__ Ain, const float* __restrict__ W,
    const float* __restrict__ bias, float* __restrict__ outp, int mode)
{
    __shared__ __align__(16) uint32_t As[2][128 * 32];  // 32 KB
    __shared__ __align__(16) uint32_t Bs[2][64 * 32];   // 16 KB

    const float* A = (mode == 3) ? g_ctx : Ain;
    const int tid = threadIdx.x;
    const int wid = tid >> 5;
    const int lid = tid & 31;
    const int wm  = wid >> 1;          // 0..3  -> m offset wm*32
    const int wn  = wid & 1;           // 0..1  -> n offset wn*32
    const int g   = lid >> 2;          // 0..7
    const int t   = lid & 3;           // 0..3

    const int m0 = blockIdx.y * 128;
    const int n0 = blockIdx.x * 64;

    const float* aP = A + (size_t)m0 * DD;
    const float* wP = W + (size_t)n0 * DD;

    float acc[2][4][4];
#pragma unroll
    for (int mt = 0; mt < 2; mt++)
#pragma unroll
        for (int nt = 0; nt < 4; nt++)
#pragma unroll
            for (int j = 0; j < 4; j++) acc[mt][nt][j] = 0.f;

    float4 stA[4], stB[2];

#define LDG_CHUNK(kc) do { \
    _Pragma("unroll") \
    for (int _i = 0; _i < 4; _i++) { \
        int _idx = tid + _i * 256; \
        int _r = _idx >> 3, _c4 = _idx & 7; \
        stA[_i] = *(const float4*)(aP + (size_t)_r * DD + (kc) * 32 + _c4 * 4); \
    } \
    _Pragma("unroll") \
    for (int _i = 0; _i < 2; _i++) { \
        int _idx = tid + _i * 256; \
        int _r = _idx >> 3, _c4 = _idx & 7; \
        stB[_i] = *(const float4*)(wP + (size_t)_r * DD + (kc) * 32 + _c4 * 4); \
    } \
} while (0)

#define STS_CHUNK(buf) do { \
    _Pragma("unroll") \
    for (int _i = 0; _i < 4; _i++) { \
        int _idx = tid + _i * 256; \
        int _r = _idx >> 3, _c4 = _idx & 7; \
        uint4 _u = make_uint4(f2tf(stA[_i].x), f2tf(stA[_i].y), \
                              f2tf(stA[_i].z), f2tf(stA[_i].w)); \
        *(uint4*)&As[buf][_r * 32 + 4 * (_c4 ^ (_r & 7))] = _u; \
    } \
    _Pragma("unroll") \
    for (int _i = 0; _i < 2; _i++) { \
        int _idx = tid + _i * 256; \
        int _r = _idx >> 3, _c4 = _idx & 7; \
        uint4 _u = make_uint4(f2tf(stB[_i].x), f2tf(stB[_i].y), \
                              f2tf(stB[_i].z), f2tf(stB[_i].w)); \
        *(uint4*)&Bs[buf][_r * 32 + 4 * (_c4 ^ (_r & 7))] = _u; \
    } \
} while (0)

    LDG_CHUNK(0);
    STS_CHUNK(0);
    __syncthreads();

    for (int c = 0; c < NCHUNK; c++) {
        const int buf = c & 1;
        if (c + 1 < NCHUNK) LDG_CHUNK(c + 1);

        const uint32_t* Ab = As[buf];
        const uint32_t* Bb = Bs[buf];
#pragma unroll
        for (int s = 0; s < 4; s++) {
            const int pk0 = (s * 8 + t) ^ (g << 2);
            const int pk1 = pk0 ^ 4;
            uint32_t af[2][4], bf[4][2];
#pragma unroll
            for (int mt = 0; mt < 2; mt++) {
                int r0 = wm * 32 + mt * 16 + g;
                af[mt][0] = Ab[r0 * 32 + pk0];
                af[mt][1] = Ab[(r0 + 8) * 32 + pk0];
                af[mt][2] = Ab[r0 * 32 + pk1];
                af[mt][3] = Ab[(r0 + 8) * 32 + pk1];
            }
#pragma unroll
            for (int nt = 0; nt < 4; nt++) {
                int nr = wn * 32 + nt * 8 + g;
                bf[nt][0] = Bb[nr * 32 + pk0];
                bf[nt][1] = Bb[nr * 32 + pk1];
            }
#pragma unroll
            for (int mt = 0; mt < 2; mt++)
#pragma unroll
                for (int nt = 0; nt < 4; nt++)
                    MMA_TF32(acc[mt][nt], af[mt], bf[nt]);
        }

        if (c + 1 < NCHUNK) STS_CHUNK(buf ^ 1);
        __syncthreads();
    }

    // epilogue: each warp writes its own C fragments (+bias)
    const int h = n0 >> 6;   // BN==HD==64, so one head per block in modes 0-2
    float* qkv = (mode == 0) ? g_q : (mode == 1) ? g_k : g_v;
#pragma unroll
    for (int mt = 0; mt < 2; mt++) {
#pragma unroll
        for (int half = 0; half < 2; half++) {
            int row = m0 + wm * 32 + mt * 16 + g + half * 8;
            int b = row / SS, sx = row % SS;
            float* dst0 = (mode == 3)
                ? (outp + (size_t)row * DD)
                : (qkv + (size_t)((b * HH + h) * SS + sx) * HDIM - n0);
            // dst0 + n gives the right element in both modes (n0..n0+63 range)
#pragma unroll
            for (int nt = 0; nt < 4; nt++) {
                int n = n0 + wn * 32 + nt * 8 + 2 * t;
                float2 bv = *(const float2*)&bias[n];
                float2 r;
                r.x = acc[mt][nt][half * 2 + 0] + bv.x;
                r.y = acc[mt][nt][half * 2 + 1] + bv.y;
                *(float2*)(dst0 + n) = r;
            }
        }
    }
}

// ============================================================================
// Flash attention (unchanged fp32 version; tensor-core port is next round)
// ============================================================================
__global__ void __launch_bounds__(256) attn_kernel()
{
    __shared__ float Qs[QT][QPITCH];
    __shared__ float Ks[KT][QPITCH];
    __shared__ float Vs[KT][QPITCH];
    __shared__ float Ps[QT][PPITCH];

    const int b  = blockIdx.z;
    const int h  = blockIdx.y;
    const int q0 = blockIdx.x * QT;
    const int tid = threadIdx.x;
    const int ty = tid >> 4;
    const int tx = tid & 15;

    const float* qb = g_q + (size_t)((b * HH + h) * SS) * HDIM;
    const float* kb = g_k + (size_t)((b * HH + h) * SS) * HDIM;
    const float* vb = g_v + (size_t)((b * HH + h) * SS) * HDIM;

#pragma unroll
    for (int i = 0; i < 4; i++) {
        int idx = tid + i * 256;
        int r = idx >> 4, c = (idx & 15) << 2;
        int qr = q0 + r;
        float4 v4 = make_float4(0.f, 0.f, 0.f, 0.f);
        if (qr < SS) v4 = *(const float4*)&qb[(size_t)qr * HDIM + c];
        *(float4*)&Qs[r][c] = v4;
    }

    float m_i[4], l_i[4], acc[4][4];
#pragma unroll
    for (int i = 0; i < 4; i++) {
        m_i[i] = -1e30f; l_i[i] = 0.f;
#pragma unroll
        for (int j = 0; j < 4; j++) acc[i][j] = 0.f;
    }
    const float scale = 0.125f;
    const int nkt = (SS + KT - 1) / KT;

    for (int kt = 0; kt < nkt; kt++) {
        int k0 = kt * KT;
#pragma unroll
        for (int i = 0; i < 2; i++) {
            int idx = tid + i * 256;
            int r = idx >> 4, c = (idx & 15) << 2;
            int kr = k0 + r;
            float4 kv4 = make_float4(0.f, 0.f, 0.f, 0.f);
            float4 vv4 = kv4;
            if (kr < SS) {
                kv4 = *(const float4*)&kb[(size_t)kr * HDIM + c];
                vv4 = *(const float4*)&vb[(size_t)kr * HDIM + c];
            }
            *(float4*)&Ks[r][c] = kv4;
            *(float4*)&Vs[r][c] = vv4;
        }
        __syncthreads();

        float s[4][2];
#pragma unroll
        for (int i = 0; i < 4; i++) { s[i][0] = 0.f; s[i][1] = 0.f; }
#pragma unroll
        for (int d4 = 0; d4 < 16; d4++) {
            float4 qv[4], kv[2];
#pragma unroll
            for (int i = 0; i < 4; i++) qv[i] = *(const float4*)&Qs[ty * 4 + i][d4 << 2];
            kv[0] = *(const float4*)&Ks[tx][d4 << 2];
            kv[1] = *(const float4*)&Ks[tx + 16][d4 << 2];
#pragma unroll
            for (int i = 0; i < 4; i++) {
#pragma unroll
                for (int j = 0; j < 2; j++) {
                    s[i][j] = fmaf(qv[i].x, kv[j].x, s[i][j]);
                    s[i][j] = fmaf(qv[i].y, kv[j].y, s[i][j]);
                    s[i][j] = fmaf(qv[i].z, kv[j].z, s[i][j]);
                    s[i][j] = fmaf(qv[i].w, kv[j].w, s[i][j]);
                }
            }
        }
#pragma unroll
        for (int i = 0; i < 4; i++) {
#pragma unroll
            for (int j = 0; j < 2; j++) {
                s[i][j] *= scale;
                if (k0 + tx + 16 * j >= SS) s[i][j] = -1e30f;
            }
        }

#pragma unroll
        for (int i = 0; i < 4; i++) {
            float mx = fmaxf(s[i][0], s[i][1]);
#pragma unroll
            for (int off = 8; off > 0; off >>= 1)
                mx = fmaxf(mx, __shfl_xor_sync(0xffffffffu, mx, off, 16));
            float mnew = fmaxf(m_i[i], mx);
            float alpha = __expf(m_i[i] - mnew);
            float p0 = __expf(s[i][0] - mnew);
            float p1 = __expf(s[i][1] - mnew);
            float ls = p0 + p1;
#pragma unroll
            for (int off = 8; off > 0; off >>= 1)
                ls += __shfl_xor_sync(0xffffffffu, ls, off, 16);
            l_i[i] = l_i[i] * alpha + ls;
            m_i[i] = mnew;
#pragma unroll
            for (int c = 0; c < 4; c++) acc[i][c] *= alpha;
            Ps[ty * 4 + i][tx]      = p0;
            Ps[ty * 4 + i][tx + 16] = p1;
        }
        __syncthreads();

#pragma unroll
        for (int k4 = 0; k4 < KT / 4; k4++) {
            float4 pv[4];
#pragma unroll
            for (int i = 0; i < 4; i++)
                pv[i] = *(const float4*)&Ps[ty * 4 + i][k4 << 2];
#pragma unroll
            for (int kk = 0; kk < 4; kk++) {
                float4 vv = *(const float4*)&Vs[(k4 << 2) + kk][tx << 2];
#pragma unroll
                for (int i = 0; i < 4; i++) {
                    float p = (kk == 0) ? pv[i].x : (kk == 1) ? pv[i].y
                            : (kk == 2) ? pv[i].z : pv[i].w;
                    acc[i][0] = fmaf(p, vv.x, acc[i][0]);
                    acc[i][1] = fmaf(p, vv.y, acc[i][1]);
                    acc[i][2] = fmaf(p, vv.z, acc[i][2]);
                    acc[i][3] = fmaf(p, vv.w, acc[i][3]);
                }
            }
        }
        __syncthreads();
    }

#pragma unroll
    for (int i = 0; i < 4; i++) {
        int qr = q0 + ty * 4 + i;
        if (qr < SS) {
            float inv = 1.0f / l_i[i];
            float4 r;
            r.x = acc[i][0] * inv; r.y = acc[i][1] * inv;
            r.z = acc[i][2] * inv; r.w = acc[i][3] * inv;
            *(float4*)&g_ctx[(size_t)(b * SS + qr) * DD + h * HDIM + (tx << 2)] = r;
        }
    }
}

// ============================================================================
extern "C" void kernel_launch(void* const* d_in, const int* in_sizes, int n_in,
                              void* d_out, int out_size)
{
    const float* x  = (const float*)d_in[0];
    const float* Wq = (const float*)d_in[1];
    const float* bq = (const float*)d_in[2];
    const float* Wk = (const float*)d_in[3];
    const float* bk = (const float*)d_in[4];
    const float* Wv = (const float*)d_in[5];
    const float* bv = (const float*)d_in[6];
    const float* Wp = (const float*)d_in[7];
    const float* bp = (const float*)d_in[8];
    float* out = (float*)d_out;

    dim3 gg(DD / 64, MTOT / 128);   // 16 x 49
    gemm_tf32<<<gg, 256>>>(x, Wq, bq, nullptr, 0);
    gemm_tf32<<<gg, 256>>>(x, Wk, bk, nullptr, 1);
    gemm_tf32<<<gg, 256>>>(x, Wv, bv, nullptr, 2);

    dim3 ga((SS + QT - 1) / QT, HH, BB);  // 25 x 16 x 4
    attn_kernel<<<ga, 256>>>();

    gemm_tf32<<<gg, 256>>>(nullptr, Wp, bp, out, 3);
}